// round 1
// baseline (speedup 1.0000x reference)
#include <cuda_runtime.h>
#include <cstdint>

#define N1C 40000
#define N2C 8000
#define DIN 256
#define HID 256

// ---------------- scratch (device globals: no allocation allowed) ----------
__device__ float g_agg1[(size_t)N1C * HID];
__device__ float g_cnt1[N1C];
__device__ float g_h1[(size_t)N1C * HID];
__device__ float g_agg2[(size_t)N2C * HID];
__device__ float g_cnt2[N2C];

// ---------------- small utility kernels ------------------------------------
__global__ void zero_kernel(float* __restrict__ p, int n) {
    int i = blockIdx.x * blockDim.x + threadIdx.x;
    if (i < n) p[i] = 0.0f;
}

__global__ void invcnt_kernel(float* __restrict__ c, int n) {
    int i = blockIdx.x * blockDim.x + threadIdx.x;
    if (i < n) c[i] = 1.0f / fmaxf(c[i], 1.0f);
}

// ---------------- edge scatter: agg[dst] += x[src], cnt[dst] += 1 ----------
__device__ __forceinline__ void red_add_v4(float4* addr, float4 v) {
    asm volatile("red.global.add.v4.f32 [%0], {%1, %2, %3, %4};"
                 :: "l"(addr), "f"(v.x), "f"(v.y), "f"(v.z), "f"(v.w)
                 : "memory");
}

// one warp per edge; 64 float4 per row (256 floats)
__global__ void scatter_kernel(const float* __restrict__ x,
                               const int* __restrict__ src,
                               const int* __restrict__ dst,
                               float* __restrict__ agg,
                               float* __restrict__ cnt,
                               int E) {
    int e = blockIdx.x * (blockDim.x >> 5) + (threadIdx.x >> 5);
    if (e >= E) return;
    int lane = threadIdx.x & 31;
    int s = __ldg(src + e);
    int d = __ldg(dst + e);
    const float4* xs = reinterpret_cast<const float4*>(x) + (size_t)s * 64;
    float4* ad = reinterpret_cast<float4*>(agg) + (size_t)d * 64;
    float4 v0 = __ldg(xs + lane);
    float4 v1 = __ldg(xs + lane + 32);
    red_add_v4(ad + lane, v0);
    red_add_v4(ad + lane + 32, v1);
    if (lane == 0) atomicAdd(cnt + d, 1.0f);
}

// ---------------- fused dual-GEMM + bias + PReLU ----------------------------
// out[m, n] = prelu( inv[m] * (A[m,:] @ Wl)[n] + (X[m,:] @ Wr)[n] + bias[n], alpha[n] )
// Implemented as one K=512 GEMM: k<256 -> (A * inv_row, Wl), k>=256 -> (X, Wr).
// BM=128, BN=128, BK=8, 256 threads, 8x8 per thread.
__global__ __launch_bounds__(256, 2)
void gemm_fused(const float* __restrict__ A, const float* __restrict__ invc,
                const float* __restrict__ X,
                const float* __restrict__ Wl, const float* __restrict__ Wr,
                const float* __restrict__ bias, const float* __restrict__ alpha,
                float* __restrict__ out, int M) {
    const int BM = 128, BN = 128, BK = 8;
    __shared__ __align__(16) float As[BK][BM + 4];   // row stride 132 floats (528B, 16B-aligned)
    __shared__ __align__(16) float Bs[BK][BN];

    int tid = threadIdx.x;
    int bm = blockIdx.x * BM;
    int bn = blockIdx.y * BN;

    // A-load mapping: thread -> (row, k-quad)
    int arow = tid >> 1;
    int akq  = tid & 1;
    // B-load mapping: thread -> (k-row, n-quad)
    int bkr = tid >> 5;
    int bnq = tid & 31;
    // compute mapping
    int tx = tid & 15;
    int ty = tid >> 4;

    float acc[8][8];
#pragma unroll
    for (int i = 0; i < 8; i++)
#pragma unroll
        for (int j = 0; j < 8; j++) acc[i][j] = 0.0f;

    for (int k0 = 0; k0 < 2 * DIN; k0 += BK) {
        // ---- load A tile (128 x 8) ----
        {
            int grow = bm + arow;
            float4 av = make_float4(0.f, 0.f, 0.f, 0.f);
            if (grow < M) {
                if (k0 < DIN) {
                    av = __ldg(reinterpret_cast<const float4*>(A + (size_t)grow * DIN + k0) + akq);
                    float s = __ldg(invc + grow);
                    av.x *= s; av.y *= s; av.z *= s; av.w *= s;
                } else {
                    av = __ldg(reinterpret_cast<const float4*>(X + (size_t)grow * DIN + (k0 - DIN)) + akq);
                }
            }
            int kk = akq * 4;
            As[kk + 0][arow] = av.x;
            As[kk + 1][arow] = av.y;
            As[kk + 2][arow] = av.z;
            As[kk + 3][arow] = av.w;
        }
        // ---- load B tile (8 x 128) ----
        {
            int gk = k0 + bkr;
            const float* W = (gk < DIN) ? Wl : Wr;
            int krow = gk & (DIN - 1);
            float4 bv = __ldg(reinterpret_cast<const float4*>(W + (size_t)krow * HID + bn) + bnq);
            *reinterpret_cast<float4*>(&Bs[bkr][bnq * 4]) = bv;
        }
        __syncthreads();

#pragma unroll
        for (int kk = 0; kk < BK; kk++) {
            float af[8], bf[8];
            *reinterpret_cast<float4*>(&af[0]) = *reinterpret_cast<const float4*>(&As[kk][ty * 4]);
            *reinterpret_cast<float4*>(&af[4]) = *reinterpret_cast<const float4*>(&As[kk][ty * 4 + 64]);
            *reinterpret_cast<float4*>(&bf[0]) = *reinterpret_cast<const float4*>(&Bs[kk][tx * 4]);
            *reinterpret_cast<float4*>(&bf[4]) = *reinterpret_cast<const float4*>(&Bs[kk][tx * 4 + 64]);
#pragma unroll
            for (int i = 0; i < 8; i++)
#pragma unroll
                for (int j = 0; j < 8; j++)
                    acc[i][j] = fmaf(af[i], bf[j], acc[i][j]);
        }
        __syncthreads();
    }

    // ---- epilogue: bias + PReLU + store ----
    float4 b0 = __ldg(reinterpret_cast<const float4*>(bias + bn + tx * 4));
    float4 b1 = __ldg(reinterpret_cast<const float4*>(bias + bn + tx * 4 + 64));
    float4 a0 = __ldg(reinterpret_cast<const float4*>(alpha + bn + tx * 4));
    float4 a1 = __ldg(reinterpret_cast<const float4*>(alpha + bn + tx * 4 + 64));
    const float bb[8] = {b0.x, b0.y, b0.z, b0.w, b1.x, b1.y, b1.z, b1.w};
    const float aa[8] = {a0.x, a0.y, a0.z, a0.w, a1.x, a1.y, a1.z, a1.w};

#pragma unroll
    for (int i = 0; i < 8; i++) {
        int gm = bm + ((i < 4) ? (ty * 4 + i) : (64 + ty * 4 + (i - 4)));
        if (gm >= M) continue;
        float c[8];
#pragma unroll
        for (int j = 0; j < 8; j++) {
            float v = acc[i][j] + bb[j];
            c[j] = (v > 0.0f) ? v : aa[j] * v;
        }
        float* op = out + (size_t)gm * HID + bn + tx * 4;
        *reinterpret_cast<float4*>(op)      = make_float4(c[0], c[1], c[2], c[3]);
        *reinterpret_cast<float4*>(op + 64) = make_float4(c[4], c[5], c[6], c[7]);
    }
}

// ---------------- launch -----------------------------------------------------
extern "C" void kernel_launch(void* const* d_in, const int* in_sizes, int n_in,
                              void* d_out, int out_size) {
    const float* x    = (const float*)d_in[0];
    const int*   src1 = (const int*)d_in[1];
    const int*   dst1 = (const int*)d_in[2];
    const int*   src2 = (const int*)d_in[3];
    const int*   dst2 = (const int*)d_in[4];

    // Locate weights: first entry (index >= 5) of size 256*256. Handles the
    // presence/absence of the n1/n2 scalar inputs in metadata order.
    int iW = 5;
    while (iW < n_in && in_sizes[iW] != DIN * HID) iW++;
    const float* W_l1 = (const float*)d_in[iW + 0];
    const float* W_r1 = (const float*)d_in[iW + 1];
    const float* b1   = (const float*)d_in[iW + 2];
    const float* a1   = (const float*)d_in[iW + 3];
    const float* W_l2 = (const float*)d_in[iW + 4];
    const float* W_r2 = (const float*)d_in[iW + 5];
    const float* b2   = (const float*)d_in[iW + 6];
    const float* a2   = (const float*)d_in[iW + 7];

    const int E1 = in_sizes[1];
    const int E2 = in_sizes[3];

    float *agg1, *cnt1, *h1, *agg2, *cnt2;
    cudaGetSymbolAddress((void**)&agg1, g_agg1);
    cudaGetSymbolAddress((void**)&cnt1, g_cnt1);
    cudaGetSymbolAddress((void**)&h1,   g_h1);
    cudaGetSymbolAddress((void**)&agg2, g_agg2);
    cudaGetSymbolAddress((void**)&cnt2, g_cnt2);

    float* out = (float*)d_out;

    // ---------------- layer 1 ----------------
    {
        int n = N1C * HID;
        zero_kernel<<<(n + 255) / 256, 256>>>(agg1, n);
        zero_kernel<<<(N1C + 255) / 256, 256>>>(cnt1, N1C);

        int wpb = 8;  // warps per block
        scatter_kernel<<<(E1 + wpb - 1) / wpb, wpb * 32>>>(x, src1, dst1, agg1, cnt1, E1);

        invcnt_kernel<<<(N1C + 255) / 256, 256>>>(cnt1, N1C);

        dim3 grid((N1C + 127) / 128, HID / 128);
        gemm_fused<<<grid, 256>>>(agg1, cnt1, x, W_l1, W_r1, b1, a1, h1, N1C);
    }

    // ---------------- layer 2 ----------------
    {
        int n = N2C * HID;
        zero_kernel<<<(n + 255) / 256, 256>>>(agg2, n);
        zero_kernel<<<(N2C + 255) / 256, 256>>>(cnt2, N2C);

        int wpb = 8;
        scatter_kernel<<<(E2 + wpb - 1) / wpb, wpb * 32>>>(h1, src2, dst2, agg2, cnt2, E2);

        invcnt_kernel<<<(N2C + 255) / 256, 256>>>(cnt2, N2C);

        dim3 grid((N2C + 127) / 128, HID / 128);
        gemm_fused<<<grid, 256>>>(agg2, cnt2, h1, W_l2, W_r2, b2, a2, out, N2C);
    }
}

// round 3
// speedup vs baseline: 1.6183x; 1.6183x over previous
#include <cuda_runtime.h>
#include <cuda_bf16.h>
#include <cstdint>

#define N1C 40000
#define N2C 8000
#define DIN 256
#define HID 256

// ---------------- scratch (device globals: no allocation allowed) ----------
__device__ __align__(16) float g_agg1[(size_t)N1C * HID];
__device__ float g_cnt1[N1C];
__device__ __align__(16) float g_h1[(size_t)N1C * HID];
__device__ __align__(16) float g_agg2[(size_t)N2C * HID];
__device__ float g_cnt2[N2C];
// packed A operand (per-layer, reused): [M][512] bf16 hi and lo planes
__device__ __align__(16) __nv_bfloat16 g_Ahi[(size_t)N1C * 512];
__device__ __align__(16) __nv_bfloat16 g_Alo[(size_t)N1C * 512];
// packed B: [layer(2)][512][256] bf16 hi and lo
__device__ __align__(16) __nv_bfloat16 g_Bhi[2 * 512 * 256];
__device__ __align__(16) __nv_bfloat16 g_Blo[2 * 512 * 256];

// ---------------- helpers ----------------------------------------------------
__device__ __forceinline__ uint32_t smem_u32(const void* p) {
    uint32_t a;
    asm("{ .reg .u64 t; cvta.to.shared.u64 t, %1; cvt.u32.u64 %0, t; }" : "=r"(a) : "l"(p));
    return a;
}
__device__ __forceinline__ void cp16(uint32_t dst, const void* src, bool pred) {
    int n = pred ? 16 : 0;
    asm volatile("cp.async.cg.shared.global [%0], [%1], 16, %2;" :: "r"(dst), "l"(src), "r"(n));
}
#define CP_COMMIT() asm volatile("cp.async.commit_group;" ::: "memory")
__device__ __forceinline__ void ldsm4(uint32_t& r0, uint32_t& r1, uint32_t& r2, uint32_t& r3, uint32_t a) {
    asm volatile("ldmatrix.sync.aligned.m8n8.x4.shared.b16 {%0,%1,%2,%3}, [%4];"
                 : "=r"(r0), "=r"(r1), "=r"(r2), "=r"(r3) : "r"(a));
}
__device__ __forceinline__ void ldsm4t(uint32_t& r0, uint32_t& r1, uint32_t& r2, uint32_t& r3, uint32_t a) {
    asm volatile("ldmatrix.sync.aligned.m8n8.x4.trans.shared.b16 {%0,%1,%2,%3}, [%4];"
                 : "=r"(r0), "=r"(r1), "=r"(r2), "=r"(r3) : "r"(a));
}
__device__ __forceinline__ void mma16816(float* c, const uint32_t* a, const uint32_t* b) {
    asm volatile("mma.sync.aligned.m16n8k16.row.col.f32.bf16.bf16.f32 "
                 "{%0,%1,%2,%3}, {%4,%5,%6,%7}, {%8,%9}, {%0,%1,%2,%3};"
                 : "+f"(c[0]), "+f"(c[1]), "+f"(c[2]), "+f"(c[3])
                 : "r"(a[0]), "r"(a[1]), "r"(a[2]), "r"(a[3]), "r"(b[0]), "r"(b[1]));
}
__device__ __forceinline__ uint32_t pack_bf2(__nv_bfloat16 a, __nv_bfloat16 b) {
    return ((uint32_t)__bfloat16_as_ushort(b) << 16) | (uint32_t)__bfloat16_as_ushort(a);
}

// ---------------- small kernels ----------------------------------------------
__global__ void invcnt_kernel(float* __restrict__ c, int n) {
    int i = blockIdx.x * blockDim.x + threadIdx.x;
    if (i < n) c[i] = 1.0f / fmaxf(c[i], 1.0f);
}

// A pack: Ahi/Alo[row][0:256) = split(agg[row]*inv[row]); [256:512) = split(X[row])
__global__ void pack_A(const float* __restrict__ agg, const float* __restrict__ invc,
                       const float* __restrict__ X,
                       __nv_bfloat16* __restrict__ Ahi, __nv_bfloat16* __restrict__ Alo, int M) {
    int idx = blockIdx.x * blockDim.x + threadIdx.x;
    if (idx >= M * 128) return;
    int row = idx >> 7;
    int col = (idx & 127) * 4;
    float4 v;
    float sc;
    if (col < 256) { v = __ldg(reinterpret_cast<const float4*>(agg + (size_t)row * 256 + col)); sc = __ldg(invc + row); }
    else           { v = __ldg(reinterpret_cast<const float4*>(X + (size_t)row * 256 + col - 256)); sc = 1.0f; }
    float f[4] = {v.x * sc, v.y * sc, v.z * sc, v.w * sc};
    __nv_bfloat16 h[4], l[4];
#pragma unroll
    for (int i = 0; i < 4; i++) {
        h[i] = __float2bfloat16(f[i]);
        l[i] = __float2bfloat16(f[i] - __bfloat162float(h[i]));
    }
    uint2 ph = make_uint2(pack_bf2(h[0], h[1]), pack_bf2(h[2], h[3]));
    uint2 pl = make_uint2(pack_bf2(l[0], l[1]), pack_bf2(l[2], l[3]));
    *reinterpret_cast<uint2*>(Ahi + (size_t)row * 512 + col) = ph;
    *reinterpret_cast<uint2*>(Alo + (size_t)row * 512 + col) = pl;
}

// B pack: B[l][k][n], k<256 -> Wl, else Wr
__global__ void pack_B(const float* __restrict__ Wl1, const float* __restrict__ Wr1,
                       const float* __restrict__ Wl2, const float* __restrict__ Wr2,
                       __nv_bfloat16* __restrict__ Bhi, __nv_bfloat16* __restrict__ Blo) {
    int idx = blockIdx.x * blockDim.x + threadIdx.x;  // 2*512*64
    if (idx >= 2 * 512 * 64) return;
    int l = idx >> 15;
    int k = (idx >> 6) & 511;
    int col = (idx & 63) * 4;
    const float* W = (l == 0) ? ((k < 256) ? Wl1 : Wr1) : ((k < 256) ? Wl2 : Wr2);
    float4 v = __ldg(reinterpret_cast<const float4*>(W + (size_t)(k & 255) * 256 + col));
    float f[4] = {v.x, v.y, v.z, v.w};
    __nv_bfloat16 h[4], lo[4];
#pragma unroll
    for (int i = 0; i < 4; i++) {
        h[i] = __float2bfloat16(f[i]);
        lo[i] = __float2bfloat16(f[i] - __bfloat162float(h[i]));
    }
    size_t o = ((size_t)l * 512 + k) * 256 + col;
    *reinterpret_cast<uint2*>(Bhi + o) = make_uint2(pack_bf2(h[0], h[1]), pack_bf2(h[2], h[3]));
    *reinterpret_cast<uint2*>(Blo + o) = make_uint2(pack_bf2(lo[0], lo[1]), pack_bf2(lo[2], lo[3]));
}

// ---------------- edge scatter -----------------------------------------------
__device__ __forceinline__ void red_add_v4(float4* addr, float4 v) {
    asm volatile("red.global.add.v4.f32 [%0], {%1, %2, %3, %4};"
                 :: "l"(addr), "f"(v.x), "f"(v.y), "f"(v.z), "f"(v.w) : "memory");
}
__global__ void scatter_kernel(const float* __restrict__ x,
                               const int* __restrict__ src,
                               const int* __restrict__ dst,
                               float* __restrict__ agg,
                               float* __restrict__ cnt, int E) {
    int e = blockIdx.x * (blockDim.x >> 5) + (threadIdx.x >> 5);
    if (e >= E) return;
    int lane = threadIdx.x & 31;
    int s = __ldg(src + e);
    int d = __ldg(dst + e);
    const float4* xs = reinterpret_cast<const float4*>(x) + (size_t)s * 64;
    float4* ad = reinterpret_cast<float4*>(agg) + (size_t)d * 64;
    float4 v0 = __ldg(xs + lane);
    float4 v1 = __ldg(xs + lane + 32);
    red_add_v4(ad + lane, v0);
    red_add_v4(ad + lane + 32, v1);
    if (lane == 0) atomicAdd(cnt + d, 1.0f);
}

// ---------------- HMMA GEMM + bias + PReLU ------------------------------------
// out[m,n] = prelu( sum_phase A_ph[m,:] @ B_ph[:,n] + bias[n], alpha[n] )
// phases: (Ahi,Bhi), (Ahi,Blo), (Alo,Bhi). K=512 per phase, BK=64, 24 iters.
#define GBM 128
#define GBN 128
#define GBK 64
#define NIT 24

__device__ __forceinline__ void gload(uint32_t sb, int buf, int tid, int bm, int M,
                                      const __nv_bfloat16* Ap, const __nv_bfloat16* Bp, int k0) {
    uint32_t sA = sb + (uint32_t)buf * 16384u;
    uint32_t sB = sb + 32768u + (uint32_t)buf * 16384u;
#pragma unroll
    for (int i = 0; i < 4; i++) {
        int row = (tid >> 3) + i * 32;
        int seg = tid & 7;
        int grow = bm + row;
        const void* src = Ap + (size_t)grow * 512 + k0 + seg * 8;
        uint32_t dst = sA + (((uint32_t)row * 128u + (uint32_t)seg * 16u) ^ (((uint32_t)row & 7u) << 4));
        cp16(dst, src, grow < M);
    }
#pragma unroll
    for (int i = 0; i < 4; i++) {
        int row = (tid >> 4) + i * 16;
        int seg = tid & 15;
        const void* src = Bp + (size_t)(k0 + row) * 256 + seg * 8;
        uint32_t dst = sB + (((uint32_t)row * 256u + (uint32_t)seg * 16u) ^ (((uint32_t)row & 7u) << 4));
        cp16(dst, src, true);
    }
    CP_COMMIT();
}

__global__ __launch_bounds__(256, 2)
void gemm_mma(const __nv_bfloat16* __restrict__ Ahi, const __nv_bfloat16* __restrict__ Alo,
              const __nv_bfloat16* __restrict__ Bhi, const __nv_bfloat16* __restrict__ Blo,
              const float* __restrict__ bias, const float* __restrict__ alpha,
              float* __restrict__ out, int M) {
    extern __shared__ char smem[];
    uint32_t sb = smem_u32(smem);
    const int tid = threadIdx.x;
    const int wid = tid >> 5, lane = tid & 31;
    const int bm = blockIdx.x * GBM;
    const int bn = blockIdx.y * GBN;
    const int m0 = (wid & 3) * 32;
    const int n0 = (wid >> 2) * 64;

    float acc[2][8][4];
#pragma unroll
    for (int i = 0; i < 2; i++)
#pragma unroll
        for (int j = 0; j < 8; j++)
#pragma unroll
            for (int r = 0; r < 4; r++) acc[i][j][r] = 0.0f;

    // phase pointer tables
    const __nv_bfloat16* Aps[3] = {Ahi, Ahi, Alo};
    const __nv_bfloat16* Bps[3] = {Bhi + bn, Blo + bn, Bhi + bn};

    gload(sb, 0, tid, bm, M, Aps[0], Bps[0], 0);

#pragma unroll 1
    for (int it = 0; it < NIT; it++) {
        int buf = it & 1;
        if (it + 1 < NIT) {
            int ph = (it + 1) >> 3;
            gload(sb, buf ^ 1, tid, bm, M, Aps[ph], Bps[ph], ((it + 1) & 7) * GBK);
            asm volatile("cp.async.wait_group 1;" ::: "memory");
        } else {
            asm volatile("cp.async.wait_group 0;" ::: "memory");
        }
        __syncthreads();

        uint32_t sA = sb + (uint32_t)buf * 16384u;
        uint32_t sB = sb + 32768u + (uint32_t)buf * 16384u;
#pragma unroll
        for (int ks = 0; ks < 4; ks++) {
            uint32_t a[2][4];
#pragma unroll
            for (int i = 0; i < 2; i++) {
                uint32_t mrow = (uint32_t)(m0 + i * 16 + (lane & 15));
                uint32_t cb = (uint32_t)(ks * 32 + (lane >> 4) * 16);
                uint32_t addr = sA + ((mrow * 128u + cb) ^ ((mrow & 7u) << 4));
                ldsm4(a[i][0], a[i][1], a[i][2], a[i][3], addr);
            }
            uint32_t b[8][2];
#pragma unroll
            for (int j2 = 0; j2 < 4; j2++) {
                uint32_t krow = (uint32_t)(ks * 16 + (lane & 15));
                uint32_t cb = (uint32_t)((n0 + j2 * 16 + (lane >> 4) * 8) * 2);
                uint32_t addr = sB + ((krow * 256u + cb) ^ ((krow & 7u) << 4));
                ldsm4t(b[j2 * 2][0], b[j2 * 2][1], b[j2 * 2 + 1][0], b[j2 * 2 + 1][1], addr);
            }
#pragma unroll
            for (int i = 0; i < 2; i++)
#pragma unroll
                for (int j = 0; j < 8; j++)
                    mma16816(acc[i][j], a[i], b[j]);
        }
        __syncthreads();
    }

    // ---- epilogue: bias + PReLU + store ----
#pragma unroll
    for (int i = 0; i < 2; i++) {
        int r0 = bm + m0 + i * 16 + (lane >> 2);
#pragma unroll
        for (int j = 0; j < 8; j++) {
            int col = bn + n0 + j * 8 + (lane & 3) * 2;
            float2 bb = __ldg(reinterpret_cast<const float2*>(bias + col));
            float2 aa = __ldg(reinterpret_cast<const float2*>(alpha + col));
            if (r0 < M) {
                float v0 = acc[i][j][0] + bb.x;
                float v1 = acc[i][j][1] + bb.y;
                v0 = v0 > 0.f ? v0 : aa.x * v0;
                v1 = v1 > 0.f ? v1 : aa.y * v1;
                *reinterpret_cast<float2*>(out + (size_t)r0 * 256 + col) = make_float2(v0, v1);
            }
            if (r0 + 8 < M) {
                float v2 = acc[i][j][2] + bb.x;
                float v3 = acc[i][j][3] + bb.y;
                v2 = v2 > 0.f ? v2 : aa.x * v2;
                v3 = v3 > 0.f ? v3 : aa.y * v3;
                *reinterpret_cast<float2*>(out + (size_t)(r0 + 8) * 256 + col) = make_float2(v2, v3);
            }
        }
    }
}

// ---------------- launch -------------------------------------------------------
extern "C" void kernel_launch(void* const* d_in, const int* in_sizes, int n_in,
                              void* d_out, int out_size) {
    const float* x    = (const float*)d_in[0];
    const int*   src1 = (const int*)d_in[1];
    const int*   dst1 = (const int*)d_in[2];
    const int*   src2 = (const int*)d_in[3];
    const int*   dst2 = (const int*)d_in[4];

    int iW = 5;
    while (iW < n_in && in_sizes[iW] != DIN * HID) iW++;
    const float* W_l1 = (const float*)d_in[iW + 0];
    const float* W_r1 = (const float*)d_in[iW + 1];
    const float* b1   = (const float*)d_in[iW + 2];
    const float* a1   = (const float*)d_in[iW + 3];
    const float* W_l2 = (const float*)d_in[iW + 4];
    const float* W_r2 = (const float*)d_in[iW + 5];
    const float* b2   = (const float*)d_in[iW + 6];
    const float* a2   = (const float*)d_in[iW + 7];

    const int E1 = in_sizes[1];
    const int E2 = in_sizes[3];

    float *agg1, *cnt1, *h1, *agg2, *cnt2;
    __nv_bfloat16 *Ahi, *Alo, *Bhi, *Blo;
    cudaGetSymbolAddress((void**)&agg1, g_agg1);
    cudaGetSymbolAddress((void**)&cnt1, g_cnt1);
    cudaGetSymbolAddress((void**)&h1,   g_h1);
    cudaGetSymbolAddress((void**)&agg2, g_agg2);
    cudaGetSymbolAddress((void**)&cnt2, g_cnt2);
    cudaGetSymbolAddress((void**)&Ahi,  g_Ahi);
    cudaGetSymbolAddress((void**)&Alo,  g_Alo);
    cudaGetSymbolAddress((void**)&Bhi,  g_Bhi);
    cudaGetSymbolAddress((void**)&Blo,  g_Blo);

    float* out = (float*)d_out;

    const int SMEM_GEMM = 65536;
    cudaFuncSetAttribute(gemm_mma, cudaFuncAttributeMaxDynamicSharedMemorySize, SMEM_GEMM);

    pack_B<<<(2 * 512 * 64 + 255) / 256, 256>>>(W_l1, W_r1, W_l2, W_r2, Bhi, Blo);

    // ---------------- layer 1 ----------------
    cudaMemsetAsync(agg1, 0, (size_t)N1C * HID * sizeof(float));
    cudaMemsetAsync(cnt1, 0, (size_t)N1C * sizeof(float));
    {
        int wpb = 8;
        scatter_kernel<<<(E1 + wpb - 1) / wpb, wpb * 32>>>(x, src1, dst1, agg1, cnt1, E1);
        invcnt_kernel<<<(N1C + 255) / 256, 256>>>(cnt1, N1C);
        pack_A<<<(N1C * 128 + 255) / 256, 256>>>(agg1, cnt1, x, Ahi, Alo, N1C);
        dim3 grid((N1C + GBM - 1) / GBM, 2);
        gemm_mma<<<grid, 256, SMEM_GEMM>>>(Ahi, Alo, Bhi, Blo, b1, a1, h1, N1C);
    }

    // ---------------- layer 2 ----------------
    cudaMemsetAsync(agg2, 0, (size_t)N2C * HID * sizeof(float));
    cudaMemsetAsync(cnt2, 0, (size_t)N2C * sizeof(float));
    {
        int wpb = 8;
        scatter_kernel<<<(E2 + wpb - 1) / wpb, wpb * 32>>>(h1, src2, dst2, agg2, cnt2, E2);
        invcnt_kernel<<<(N2C + 255) / 256, 256>>>(cnt2, N2C);
        pack_A<<<(N2C * 128 + 255) / 256, 256>>>(agg2, cnt2, h1, Ahi, Alo, N2C);
        dim3 grid((N2C + GBM - 1) / GBM, 2);
        gemm_mma<<<grid, 256, SMEM_GEMM>>>(Ahi, Alo, Bhi + 512 * 256, Blo + 512 * 256, b2, a2, out, N2C);
    }
}

// round 4
// speedup vs baseline: 1.7491x; 1.0808x over previous
#include <cuda_runtime.h>
#include <cuda_bf16.h>
#include <cstdint>

#define N1C 40000
#define N2C 8000
#define E1C 1000000
#define E2C 200000
#define DIN 256
#define HID 256

// ---------------- scratch (device globals: no allocation allowed) ----------
__device__ __align__(16) float g_h1[(size_t)N1C * HID];
// packed A operand (per-layer, reused): [M][512] bf16 hi and lo planes
__device__ __align__(16) __nv_bfloat16 g_Ahi[(size_t)N1C * 512];
__device__ __align__(16) __nv_bfloat16 g_Alo[(size_t)N1C * 512];
// packed B: [layer(2)][512][256] bf16 hi and lo
__device__ __align__(16) __nv_bfloat16 g_Bhi[2 * 512 * 256];
__device__ __align__(16) __nv_bfloat16 g_Blo[2 * 512 * 256];
// edge binning scratch
__device__ int g_hist[N1C];
__device__ int g_off1[N1C + 1];
__device__ int g_cur1[N1C];
__device__ int g_off2[N2C + 1];
__device__ int g_cur2[N2C];
__device__ int g_ss1[E1C];
__device__ int g_ss2[E2C];

// ---------------- helpers ----------------------------------------------------
__device__ __forceinline__ uint32_t smem_u32(const void* p) {
    uint32_t a;
    asm("{ .reg .u64 t; cvta.to.shared.u64 t, %1; cvt.u32.u64 %0, t; }" : "=r"(a) : "l"(p));
    return a;
}
__device__ __forceinline__ void cp16(uint32_t dst, const void* src, bool pred) {
    int n = pred ? 16 : 0;
    asm volatile("cp.async.cg.shared.global [%0], [%1], 16, %2;" :: "r"(dst), "l"(src), "r"(n));
}
#define CP_COMMIT() asm volatile("cp.async.commit_group;" ::: "memory")
__device__ __forceinline__ void ldsm4(uint32_t& r0, uint32_t& r1, uint32_t& r2, uint32_t& r3, uint32_t a) {
    asm volatile("ldmatrix.sync.aligned.m8n8.x4.shared.b16 {%0,%1,%2,%3}, [%4];"
                 : "=r"(r0), "=r"(r1), "=r"(r2), "=r"(r3) : "r"(a));
}
__device__ __forceinline__ void ldsm4t(uint32_t& r0, uint32_t& r1, uint32_t& r2, uint32_t& r3, uint32_t a) {
    asm volatile("ldmatrix.sync.aligned.m8n8.x4.trans.shared.b16 {%0,%1,%2,%3}, [%4];"
                 : "=r"(r0), "=r"(r1), "=r"(r2), "=r"(r3) : "r"(a));
}
__device__ __forceinline__ void mma16816(float* c, const uint32_t* a, const uint32_t* b) {
    asm volatile("mma.sync.aligned.m16n8k16.row.col.f32.bf16.bf16.f32 "
                 "{%0,%1,%2,%3}, {%4,%5,%6,%7}, {%8,%9}, {%0,%1,%2,%3};"
                 : "+f"(c[0]), "+f"(c[1]), "+f"(c[2]), "+f"(c[3])
                 : "r"(a[0]), "r"(a[1]), "r"(a[2]), "r"(a[3]), "r"(b[0]), "r"(b[1]));
}
__device__ __forceinline__ uint32_t pack_bf2(__nv_bfloat16 a, __nv_bfloat16 b) {
    return ((uint32_t)__bfloat16_as_ushort(b) << 16) | (uint32_t)__bfloat16_as_ushort(a);
}
// split 4 fp32 -> hi/lo bf16, store as uint2 each
__device__ __forceinline__ void store_split(__nv_bfloat16* Ahi, __nv_bfloat16* Alo,
                                            size_t o, float4 v) {
    __nv_bfloat16 h0 = __float2bfloat16(v.x), h1 = __float2bfloat16(v.y);
    __nv_bfloat16 h2 = __float2bfloat16(v.z), h3 = __float2bfloat16(v.w);
    __nv_bfloat16 l0 = __float2bfloat16(v.x - __bfloat162float(h0));
    __nv_bfloat16 l1 = __float2bfloat16(v.y - __bfloat162float(h1));
    __nv_bfloat16 l2 = __float2bfloat16(v.z - __bfloat162float(h2));
    __nv_bfloat16 l3 = __float2bfloat16(v.w - __bfloat162float(h3));
    *reinterpret_cast<uint2*>(Ahi + o) = make_uint2(pack_bf2(h0, h1), pack_bf2(h2, h3));
    *reinterpret_cast<uint2*>(Alo + o) = make_uint2(pack_bf2(l0, l1), pack_bf2(l2, l3));
}

// ---------------- binning kernels ---------------------------------------------
__global__ void hist_kernel(const int* __restrict__ dst, int E, int* __restrict__ hist) {
    int i = blockIdx.x * blockDim.x + threadIdx.x;
    if (i < E) atomicAdd(hist + __ldg(dst + i), 1);
}

// single-block exclusive scan over n bins -> off[0..n], cur[i]=off[i]
__global__ void scan_kernel(const int* __restrict__ hist, int n,
                            int* __restrict__ off, int* __restrict__ cur) {
    __shared__ int part[1024];
    int t = threadIdx.x;
    int chunk = (n + 1023) >> 10;
    int b = t * chunk;
    int s = 0;
    for (int i = 0; i < chunk; i++) if (b + i < n) s += hist[b + i];
    part[t] = s;
    __syncthreads();
#pragma unroll
    for (int d = 1; d < 1024; d <<= 1) {
        int v = (t >= d) ? part[t - d] : 0;
        __syncthreads();
        part[t] += v;
        __syncthreads();
    }
    int run = (t ? part[t - 1] : 0);
    for (int i = 0; i < chunk; i++) {
        int idx = b + i;
        if (idx < n) { off[idx] = run; cur[idx] = run; run += hist[idx]; }
    }
    if (t == 1023) off[n] = part[1023];
}

__global__ void reorder_kernel(const int* __restrict__ src, const int* __restrict__ dst,
                               int E, int* __restrict__ cur, int* __restrict__ ssrc) {
    int i = blockIdx.x * blockDim.x + threadIdx.x;
    if (i >= E) return;
    int pos = atomicAdd(cur + __ldg(dst + i), 1);
    ssrc[pos] = __ldg(src + i);
}

// ---------------- segmented gather-mean + bf16 split pack ----------------------
// warp per target row: Ahi/Alo[row][0:256) = split(mean_{e in seg} x[src_e]);
//                      Ahi/Alo[row][256:512) = split(xt[row])
__global__ __launch_bounds__(256)
void agg_pack(const float* __restrict__ x, const float* __restrict__ xt,
              const int* __restrict__ ssrc, const int* __restrict__ off,
              __nv_bfloat16* __restrict__ Ahi, __nv_bfloat16* __restrict__ Alo, int n_tgt) {
    int w = (blockIdx.x * blockDim.x + threadIdx.x) >> 5;
    if (w >= n_tgt) return;
    int lane = threadIdx.x & 31;
    int s0 = __ldg(off + w), s1 = __ldg(off + w + 1);

    float4 A0 = make_float4(0.f, 0.f, 0.f, 0.f);
    float4 A1 = make_float4(0.f, 0.f, 0.f, 0.f);
    int e = s0;
    for (; e + 2 <= s1; e += 2) {
        int sa = __ldg(ssrc + e);
        int sb = __ldg(ssrc + e + 1);
        const float4* pa = reinterpret_cast<const float4*>(x) + (size_t)sa * 64;
        const float4* pb = reinterpret_cast<const float4*>(x) + (size_t)sb * 64;
        float4 a0 = __ldg(pa + lane), a1 = __ldg(pa + lane + 32);
        float4 b0 = __ldg(pb + lane), b1 = __ldg(pb + lane + 32);
        A0.x += a0.x + b0.x; A0.y += a0.y + b0.y; A0.z += a0.z + b0.z; A0.w += a0.w + b0.w;
        A1.x += a1.x + b1.x; A1.y += a1.y + b1.y; A1.z += a1.z + b1.z; A1.w += a1.w + b1.w;
    }
    if (e < s1) {
        int sa = __ldg(ssrc + e);
        const float4* pa = reinterpret_cast<const float4*>(x) + (size_t)sa * 64;
        float4 a0 = __ldg(pa + lane), a1 = __ldg(pa + lane + 32);
        A0.x += a0.x; A0.y += a0.y; A0.z += a0.z; A0.w += a0.w;
        A1.x += a1.x; A1.y += a1.y; A1.z += a1.z; A1.w += a1.w;
    }
    float inv = 1.0f / fmaxf((float)(s1 - s0), 1.0f);
    A0.x *= inv; A0.y *= inv; A0.z *= inv; A0.w *= inv;
    A1.x *= inv; A1.y *= inv; A1.z *= inv; A1.w *= inv;

    size_t rb = (size_t)w * 512 + lane * 4;
    store_split(Ahi, Alo, rb, A0);
    store_split(Ahi, Alo, rb + 128, A1);

    // root/X part
    const float4* px = reinterpret_cast<const float4*>(xt) + (size_t)w * 64;
    float4 X0 = __ldg(px + lane), X1 = __ldg(px + lane + 32);
    store_split(Ahi, Alo, rb + 256, X0);
    store_split(Ahi, Alo, rb + 384, X1);
}

// ---------------- B pack --------------------------------------------------------
__global__ void pack_B(const float* __restrict__ Wl1, const float* __restrict__ Wr1,
                       const float* __restrict__ Wl2, const float* __restrict__ Wr2,
                       __nv_bfloat16* __restrict__ Bhi, __nv_bfloat16* __restrict__ Blo) {
    int idx = blockIdx.x * blockDim.x + threadIdx.x;  // 2*512*64
    if (idx >= 2 * 512 * 64) return;
    int l = idx >> 15;
    int k = (idx >> 6) & 511;
    int col = (idx & 63) * 4;
    const float* W = (l == 0) ? ((k < 256) ? Wl1 : Wr1) : ((k < 256) ? Wl2 : Wr2);
    float4 v = __ldg(reinterpret_cast<const float4*>(W + (size_t)(k & 255) * 256 + col));
    size_t o = ((size_t)l * 512 + k) * 256 + col;
    store_split(Bhi, Blo, o, v);
}

// ---------------- HMMA GEMM + bias + PReLU ------------------------------------
#define GBM 128
#define GBN 128
#define GBK 64
#define NIT 24

__device__ __forceinline__ void gload(uint32_t sb, int buf, int tid, int bm, int M,
                                      const __nv_bfloat16* Ap, const __nv_bfloat16* Bp, int k0) {
    uint32_t sA = sb + (uint32_t)buf * 16384u;
    uint32_t sB = sb + 32768u + (uint32_t)buf * 16384u;
#pragma unroll
    for (int i = 0; i < 4; i++) {
        int row = (tid >> 3) + i * 32;
        int seg = tid & 7;
        int grow = bm + row;
        const void* src = Ap + (size_t)grow * 512 + k0 + seg * 8;
        uint32_t dst = sA + (((uint32_t)row * 128u + (uint32_t)seg * 16u) ^ (((uint32_t)row & 7u) << 4));
        cp16(dst, src, grow < M);
    }
#pragma unroll
    for (int i = 0; i < 4; i++) {
        int row = (tid >> 4) + i * 16;
        int seg = tid & 15;
        const void* src = Bp + (size_t)(k0 + row) * 256 + seg * 8;
        uint32_t dst = sB + (((uint32_t)row * 256u + (uint32_t)seg * 16u) ^ (((uint32_t)row & 7u) << 4));
        cp16(dst, src, true);
    }
    CP_COMMIT();
}

__global__ __launch_bounds__(256, 2)
void gemm_mma(const __nv_bfloat16* __restrict__ Ahi, const __nv_bfloat16* __restrict__ Alo,
              const __nv_bfloat16* __restrict__ Bhi, const __nv_bfloat16* __restrict__ Blo,
              const float* __restrict__ bias, const float* __restrict__ alpha,
              float* __restrict__ out, int M) {
    extern __shared__ char smem[];
    uint32_t sb = smem_u32(smem);
    const int tid = threadIdx.x;
    const int wid = tid >> 5, lane = tid & 31;
    const int bm = blockIdx.x * GBM;
    const int bn = blockIdx.y * GBN;
    const int m0 = (wid & 3) * 32;
    const int n0 = (wid >> 2) * 64;

    float acc[2][8][4];
#pragma unroll
    for (int i = 0; i < 2; i++)
#pragma unroll
        for (int j = 0; j < 8; j++)
#pragma unroll
            for (int r = 0; r < 4; r++) acc[i][j][r] = 0.0f;

    const __nv_bfloat16* Aps[3] = {Ahi, Ahi, Alo};
    const __nv_bfloat16* Bps[3] = {Bhi + bn, Blo + bn, Bhi + bn};

    gload(sb, 0, tid, bm, M, Aps[0], Bps[0], 0);

#pragma unroll 1
    for (int it = 0; it < NIT; it++) {
        int buf = it & 1;
        if (it + 1 < NIT) {
            int ph = (it + 1) >> 3;
            gload(sb, buf ^ 1, tid, bm, M, Aps[ph], Bps[ph], ((it + 1) & 7) * GBK);
            asm volatile("cp.async.wait_group 1;" ::: "memory");
        } else {
            asm volatile("cp.async.wait_group 0;" ::: "memory");
        }
        __syncthreads();

        uint32_t sA = sb + (uint32_t)buf * 16384u;
        uint32_t sB = sb + 32768u + (uint32_t)buf * 16384u;
#pragma unroll
        for (int ks = 0; ks < 4; ks++) {
            uint32_t a[2][4];
#pragma unroll
            for (int i = 0; i < 2; i++) {
                uint32_t mrow = (uint32_t)(m0 + i * 16 + (lane & 15));
                uint32_t cb = (uint32_t)(ks * 32 + (lane >> 4) * 16);
                uint32_t addr = sA + ((mrow * 128u + cb) ^ ((mrow & 7u) << 4));
                ldsm4(a[i][0], a[i][1], a[i][2], a[i][3], addr);
            }
            uint32_t b[8][2];
#pragma unroll
            for (int j2 = 0; j2 < 4; j2++) {
                uint32_t krow = (uint32_t)(ks * 16 + (lane & 15));
                uint32_t cb = (uint32_t)((n0 + j2 * 16 + (lane >> 4) * 8) * 2);
                uint32_t addr = sB + ((krow * 256u + cb) ^ ((krow & 7u) << 4));
                ldsm4t(b[j2 * 2][0], b[j2 * 2][1], b[j2 * 2 + 1][0], b[j2 * 2 + 1][1], addr);
            }
#pragma unroll
            for (int i = 0; i < 2; i++)
#pragma unroll
                for (int j = 0; j < 8; j++)
                    mma16816(acc[i][j], a[i], b[j]);
        }
        __syncthreads();
    }

#pragma unroll
    for (int i = 0; i < 2; i++) {
        int r0 = bm + m0 + i * 16 + (lane >> 2);
#pragma unroll
        for (int j = 0; j < 8; j++) {
            int col = bn + n0 + j * 8 + (lane & 3) * 2;
            float2 bb = __ldg(reinterpret_cast<const float2*>(bias + col));
            float2 aa = __ldg(reinterpret_cast<const float2*>(alpha + col));
            if (r0 < M) {
                float v0 = acc[i][j][0] + bb.x;
                float v1 = acc[i][j][1] + bb.y;
                v0 = v0 > 0.f ? v0 : aa.x * v0;
                v1 = v1 > 0.f ? v1 : aa.y * v1;
                *reinterpret_cast<float2*>(out + (size_t)r0 * 256 + col) = make_float2(v0, v1);
            }
            if (r0 + 8 < M) {
                float v2 = acc[i][j][2] + bb.x;
                float v3 = acc[i][j][3] + bb.y;
                v2 = v2 > 0.f ? v2 : aa.x * v2;
                v3 = v3 > 0.f ? v3 : aa.y * v3;
                *reinterpret_cast<float2*>(out + (size_t)(r0 + 8) * 256 + col) = make_float2(v2, v3);
            }
        }
    }
}

// ---------------- launch -------------------------------------------------------
extern "C" void kernel_launch(void* const* d_in, const int* in_sizes, int n_in,
                              void* d_out, int out_size) {
    const float* x    = (const float*)d_in[0];
    const int*   src1 = (const int*)d_in[1];
    const int*   dst1 = (const int*)d_in[2];
    const int*   src2 = (const int*)d_in[3];
    const int*   dst2 = (const int*)d_in[4];

    int iW = 5;
    while (iW < n_in && in_sizes[iW] != DIN * HID) iW++;
    const float* W_l1 = (const float*)d_in[iW + 0];
    const float* W_r1 = (const float*)d_in[iW + 1];
    const float* b1   = (const float*)d_in[iW + 2];
    const float* a1   = (const float*)d_in[iW + 3];
    const float* W_l2 = (const float*)d_in[iW + 4];
    const float* W_r2 = (const float*)d_in[iW + 5];
    const float* b2   = (const float*)d_in[iW + 6];
    const float* a2   = (const float*)d_in[iW + 7];

    const int E1 = in_sizes[1];
    const int E2 = in_sizes[3];

    float* h1;
    __nv_bfloat16 *Ahi, *Alo, *Bhi, *Blo;
    int *hist, *off1, *cur1, *off2, *cur2, *ss1, *ss2;
    cudaGetSymbolAddress((void**)&h1,   g_h1);
    cudaGetSymbolAddress((void**)&Ahi,  g_Ahi);
    cudaGetSymbolAddress((void**)&Alo,  g_Alo);
    cudaGetSymbolAddress((void**)&Bhi,  g_Bhi);
    cudaGetSymbolAddress((void**)&Blo,  g_Blo);
    cudaGetSymbolAddress((void**)&hist, g_hist);
    cudaGetSymbolAddress((void**)&off1, g_off1);
    cudaGetSymbolAddress((void**)&cur1, g_cur1);
    cudaGetSymbolAddress((void**)&off2, g_off2);
    cudaGetSymbolAddress((void**)&cur2, g_cur2);
    cudaGetSymbolAddress((void**)&ss1,  g_ss1);
    cudaGetSymbolAddress((void**)&ss2,  g_ss2);

    float* out = (float*)d_out;

    const int SMEM_GEMM = 65536;
    cudaFuncSetAttribute(gemm_mma, cudaFuncAttributeMaxDynamicSharedMemorySize, SMEM_GEMM);

    pack_B<<<(2 * 512 * 64 + 255) / 256, 256>>>(W_l1, W_r1, W_l2, W_r2, Bhi, Blo);

    // ---------------- layer 1 ----------------
    cudaMemsetAsync(hist, 0, N1C * sizeof(int));
    hist_kernel<<<(E1 + 255) / 256, 256>>>(dst1, E1, hist);
    scan_kernel<<<1, 1024>>>(hist, N1C, off1, cur1);
    reorder_kernel<<<(E1 + 255) / 256, 256>>>(src1, dst1, E1, cur1, ss1);
    agg_pack<<<(N1C + 7) / 8, 256>>>(x, x, ss1, off1, Ahi, Alo, N1C);
    {
        dim3 grid((N1C + GBM - 1) / GBM, 2);
        gemm_mma<<<grid, 256, SMEM_GEMM>>>(Ahi, Alo, Bhi, Blo, b1, a1, h1, N1C);
    }

    // ---------------- layer 2 ----------------
    cudaMemsetAsync(hist, 0, N2C * sizeof(int));
    hist_kernel<<<(E2 + 255) / 256, 256>>>(dst2, E2, hist);
    scan_kernel<<<1, 1024>>>(hist, N2C, off2, cur2);
    reorder_kernel<<<(E2 + 255) / 256, 256>>>(src2, dst2, E2, cur2, ss2);
    agg_pack<<<(N2C + 7) / 8, 256>>>(h1, h1, ss2, off2, Ahi, Alo, N2C);
    {
        dim3 grid((N2C + GBM - 1) / GBM, 2);
        gemm_mma<<<grid, 256, SMEM_GEMM>>>(Ahi, Alo, Bhi + 512 * 256, Blo + 512 * 256, b2, a2, out, N2C);
    }
}